// round 14
// baseline (speedup 1.0000x reference)
#include <cuda_runtime.h>
#include <cuda_fp16.h>
#include <stdint.h>

#define B 4
#define S 2048
#define E 256
#define H 8
#define D 32
#define M (B*S)
#define NSPLIT 2
// SCALE * log2(e), folded into Wq at decomposition time
#define CEXP (0.17677669529663687f * 1.44269504088896341f)

// ---------------- scratch (device globals; no allocation allowed) ----------
static __device__ __align__(16) __half g_q16[M*E];
static __device__ __align__(16) __half g_khi[M*E];
static __device__ __align__(16) __half g_klo[M*E];
static __device__ __align__(16) __half g_vhi[M*E];
static __device__ __align__(16) __half g_vlo[M*E];
static __device__ __align__(16) __half g_p16[M*E];
static __device__ __align__(16) __half g_whi[4*E*E];
static __device__ __align__(16) __half g_wlo[4*E*E];
static __device__ __align__(16) float g_pacc[NSPLIT*M*E];
static __device__ __align__(16) float g_plsum[NSPLIT*B*S*H];
static __device__ int g_len[B];

// ---------------- helpers ----------------------------------------------------
__device__ __forceinline__ uint32_t smem_u32(const void* p) {
    uint32_t a;
    asm("{ .reg .u64 t; cvta.to.shared.u64 t, %1; cvt.u32.u64 %0, t; }"
        : "=r"(a) : "l"(p));
    return a;
}

__device__ __forceinline__ void ldsm4(uint32_t* r, uint32_t addr) {
    asm volatile("ldmatrix.sync.aligned.m8n8.x4.shared.b16 {%0,%1,%2,%3}, [%4];"
                 : "=r"(r[0]), "=r"(r[1]), "=r"(r[2]), "=r"(r[3]) : "r"(addr));
}

__device__ __forceinline__ void ldsm4t(uint32_t* r, uint32_t addr) {
    asm volatile("ldmatrix.sync.aligned.m8n8.x4.trans.shared.b16 {%0,%1,%2,%3}, [%4];"
                 : "=r"(r[0]), "=r"(r[1]), "=r"(r[2]), "=r"(r[3]) : "r"(addr));
}

// fp16 MMA
__device__ __forceinline__ void mma16816h(float* d, const uint32_t* a,
                                          uint32_t b0, uint32_t b1) {
    asm volatile(
        "mma.sync.aligned.m16n8k16.row.col.f32.f16.f16.f32 "
        "{%0,%1,%2,%3}, {%4,%5,%6,%7}, {%8,%9}, {%0,%1,%2,%3};"
        : "+f"(d[0]), "+f"(d[1]), "+f"(d[2]), "+f"(d[3])
        : "r"(a[0]), "r"(a[1]), "r"(a[2]), "r"(a[3]), "r"(b0), "r"(b1));
}

__device__ __forceinline__ float ex2(float x) {
    float y;
    asm("ex2.approx.ftz.f32 %0, %1;" : "=f"(y) : "f"(x));
    return y;
}

__device__ __forceinline__ void cpasync16(uint32_t saddr, const void* g) {
    asm volatile("cp.async.cg.shared.global [%0], [%1], 16;"
                 :: "r"(saddr), "l"(g));
}
#define CP_COMMIT() asm volatile("cp.async.commit_group;" ::: "memory")
#define CP_WAIT0()  asm volatile("cp.async.wait_group 0;" ::: "memory")
#define CP_WAIT1()  asm volatile("cp.async.wait_group 1;" ::: "memory")

// fp16 pack helpers
__device__ __forceinline__ uint32_t pack_f16(float a, float b) {
    uint32_t h;
    asm("cvt.rn.f16x2.f32 %0, %1, %2;" : "=r"(h) : "f"(b), "f"(a));
    return h;
}
__device__ __forceinline__ void split_pair_f16(float a, float b,
                                               uint32_t& hi, uint32_t& lo) {
    uint32_t h = pack_f16(a, b);
    float ha, hb;
    asm("{\n .reg .f16 x, y;\n mov.b32 {x, y}, %2;\n"
        " cvt.f32.f16 %0, x;\n cvt.f32.f16 %1, y;\n}"
        : "=f"(ha), "=f"(hb) : "r"(h));
    lo = pack_f16(a - ha, b - hb);
    hi = h;
}

// load 8 fp32 and pack to 8 fp16 (16B payload)
__device__ __forceinline__ float4 ld_cvt8(const float* p) {
    float4 a = *(const float4*)p;
    float4 b = *(const float4*)(p + 4);
    float4 r;
    ((uint32_t*)&r)[0] = pack_f16(a.x, a.y);
    ((uint32_t*)&r)[1] = pack_f16(a.z, a.w);
    ((uint32_t*)&r)[2] = pack_f16(b.x, b.y);
    ((uint32_t*)&r)[3] = pack_f16(b.z, b.w);
    return r;
}

// ---------------- lengths ----------------------------------------------------
__global__ void len_kernel(const int* __restrict__ mask) {
    int b = blockIdx.x;
    int t = threadIdx.x;
    int s = 0;
    for (int i = t; i < S; i += 256) s += mask[b*S + i];
    __shared__ int sh[256];
    sh[t] = s;
    __syncthreads();
    for (int o = 128; o > 0; o >>= 1) {
        if (t < o) sh[t] += sh[t + o];
        __syncthreads();
    }
    if (t == 0) g_len[b] = sh[0];
}

// all 4 weight matrices, fp16 hi/lo; Wq (y==0) pre-scaled by CEXP
__global__ __launch_bounds__(256)
void decompw_kernel(const float* __restrict__ w0, const float* __restrict__ w1,
                    const float* __restrict__ w2, const float* __restrict__ w3,
                    __half* __restrict__ hi, __half* __restrict__ lo) {
    int m = blockIdx.y;
    const float* src = (m == 0) ? w0 : (m == 1) ? w1 : (m == 2) ? w2 : w3;
    float sc = (m == 0) ? CEXP : 1.0f;
    int i = blockIdx.x * 256 + threadIdx.x;           // over E*E/4
    float4 v = ((const float4*)src)[i];
    float f[4] = {v.x * sc, v.y * sc, v.z * sc, v.w * sc};
    size_t base = (size_t)m * E * E + 4 * (size_t)i;
    uint32_t h0, l0, h1, l1;
    split_pair_f16(f[0], f[1], h0, l0);
    split_pair_f16(f[2], f[3], h1, l1);
    *(uint32_t*)(hi + base) = h0;  *(uint32_t*)(hi + base + 2) = h1;
    *(uint32_t*)(lo + base) = l0;  *(uint32_t*)(lo + base + 2) = l1;
}

// ---------------- fp16x2 GEMM core: Y[m,n] = sum_k X[m,k] W[n,k] -------------
// A single fp16 (from __half array, or converted on-the-fly from fp32),
// W fp16 hi/lo (2-term). CTA 128x128, 512 threads, warp 32x32, K chunks of 64
// double-buffered via register prefetch.
#define GPITCH 144
#define GCHUNKB (128 * GPITCH)
#define GBUFB (3 * GCHUNKB)                    // A | Bh | Bl
#define GEMM_SMEM (2 * GBUFB)                  // 110592

__device__ __forceinline__ void gemm_core(
    const __half* __restrict__ Ah, const float* __restrict__ Af,
    const __half* __restrict__ Bhi, const __half* __restrict__ Blo,
    float* __restrict__ Yf,
    __half* __restrict__ Yhi, __half* __restrict__ Ylo,
    char* smem, int mode) {            // mode: 0=fp32, 1=fp16 hi/lo, 2=fp16 single
    const int bm = blockIdx.x * 128;
    const int bn = blockIdx.y * 128;
    const int tid = threadIdx.x;
    const int lane = tid & 31;
    const int wid = tid >> 5;
    const int wm = (wid & 3) * 32;
    const int wn = (wid >> 2) * 32;
    const uint32_t base = smem_u32(smem);

    float acc[2][4][4];
    #pragma unroll
    for (int mi = 0; mi < 2; mi++)
        #pragma unroll
        for (int ni = 0; ni < 4; ni++)
            #pragma unroll
            for (int k = 0; k < 4; k++) acc[mi][ni][k] = 0.f;

    const int a_row = lane & 15;
    const int a_kb  = (lane >> 4) * 16;
    const int pr0 = tid >> 3, pc0 = tid & 7;
    const int pr1 = (tid + 512) >> 3, pc1 = (tid + 512) & 7;

    float4 pf[6];
    #define PFLOAD(k0) do { \
        if (Af) { \
            pf[0] = ld_cvt8(Af + (size_t)(bm + pr0) * E + (k0) + pc0 * 8); \
            pf[3] = ld_cvt8(Af + (size_t)(bm + pr1) * E + (k0) + pc1 * 8); \
        } else { \
            pf[0] = *(const float4*)(Ah + (size_t)(bm + pr0) * E + (k0) + pc0 * 8); \
            pf[3] = *(const float4*)(Ah + (size_t)(bm + pr1) * E + (k0) + pc1 * 8); \
        } \
        size_t g0 = (size_t)pr0 * E + (k0) + pc0 * 8; \
        size_t g1 = (size_t)pr1 * E + (k0) + pc1 * 8; \
        pf[1] = *(const float4*)(Bhi + (size_t)bn * E + g0); \
        pf[2] = *(const float4*)(Blo + (size_t)bn * E + g0); \
        pf[4] = *(const float4*)(Bhi + (size_t)bn * E + g1); \
        pf[5] = *(const float4*)(Blo + (size_t)bn * E + g1); \
    } while (0)
    #define PFSTORE(buf) do { \
        char* bp = smem + (buf) * GBUFB; \
        int s0 = pr0 * GPITCH + pc0 * 16; \
        int s1 = pr1 * GPITCH + pc1 * 16; \
        *(float4*)(bp + s0)               = pf[0]; \
        *(float4*)(bp + GCHUNKB + s0)     = pf[1]; \
        *(float4*)(bp + 2 * GCHUNKB + s0) = pf[2]; \
        *(float4*)(bp + s1)               = pf[3]; \
        *(float4*)(bp + GCHUNKB + s1)     = pf[4]; \
        *(float4*)(bp + 2 * GCHUNKB + s1) = pf[5]; \
    } while (0)

    PFLOAD(0);
    PFSTORE(0);
    __syncthreads();

    for (int kc = 0; kc < 4; kc++) {
        if (kc < 3) PFLOAD((kc + 1) * 64);
        const uint32_t uA = base + (kc & 1) * GBUFB;
        const uint32_t uB = uA + GCHUNKB;

        #pragma unroll
        for (int ks = 0; ks < 4; ks++) {
            const int kb = ks * 32;
            uint32_t a[2][4], bhi[4][2], blo[4][2];
            #pragma unroll
            for (int mi = 0; mi < 2; mi++) {
                uint32_t off = (uint32_t)((wm + mi * 16 + a_row) * GPITCH + kb + a_kb);
                ldsm4(a[mi], uA + off);
            }
            #pragma unroll
            for (int np = 0; np < 2; np++) {
                uint32_t off = (uint32_t)((wn + np * 16 + a_row) * GPITCH + kb + a_kb);
                uint32_t th[4], tl[4];
                ldsm4(th, uB + off);
                ldsm4(tl, uB + GCHUNKB + off);
                bhi[np*2][0] = th[0]; bhi[np*2][1] = th[2];
                bhi[np*2+1][0] = th[1]; bhi[np*2+1][1] = th[3];
                blo[np*2][0] = tl[0]; blo[np*2][1] = tl[2];
                blo[np*2+1][0] = tl[1]; blo[np*2+1][1] = tl[3];
            }
            #pragma unroll
            for (int mi = 0; mi < 2; mi++)
                #pragma unroll
                for (int ni = 0; ni < 4; ni++) {
                    mma16816h(acc[mi][ni], a[mi], bhi[ni][0], bhi[ni][1]);
                    mma16816h(acc[mi][ni], a[mi], blo[ni][0], blo[ni][1]);
                }
        }
        if (kc < 3) {
            PFSTORE((kc + 1) & 1);
            __syncthreads();
        }
    }

    const int g = lane >> 2;
    const int t2 = (lane & 3) * 2;
    #pragma unroll
    for (int mi = 0; mi < 2; mi++)
        #pragma unroll
        for (int ni = 0; ni < 4; ni++) {
            int row = bm + wm + mi * 16 + g;
            int col = bn + wn + ni * 8 + t2;
            float* ac = acc[mi][ni];
            if (mode == 0) {
                *(float2*)&Yf[(size_t)row * E + col] = make_float2(ac[0], ac[1]);
                *(float2*)&Yf[(size_t)(row + 8) * E + col] = make_float2(ac[2], ac[3]);
            } else if (mode == 2) {
                *(uint32_t*)(Yhi + (size_t)row * E + col) = pack_f16(ac[0], ac[1]);
                *(uint32_t*)(Yhi + (size_t)(row + 8) * E + col) = pack_f16(ac[2], ac[3]);
            } else {
                uint32_t h0, l0, h1, l1;
                split_pair_f16(ac[0], ac[1], h0, l0);
                split_pair_f16(ac[2], ac[3], h1, l1);
                *(uint32_t*)(Yhi + (size_t)row * E + col) = h0;
                *(uint32_t*)(Ylo + (size_t)row * E + col) = l0;
                *(uint32_t*)(Yhi + (size_t)(row + 8) * E + col) = h1;
                *(uint32_t*)(Ylo + (size_t)(row + 8) * E + col) = l1;
            }
        }
    #undef PFLOAD
    #undef PFSTORE
}

struct QKVOuts {
    __half *q, *kh, *kl, *vh, *vl;
};

// fused Q/K/V projections from fp32 x: z=0 Q (fp16), z=1 K (hi/lo), z=2 V (hi/lo)
__global__ __launch_bounds__(512, 1)
void gemm_qkv(const float* __restrict__ x,
              const __half* __restrict__ whi, const __half* __restrict__ wlo,
              QKVOuts o) {
    extern __shared__ char smem[];
    const int z = blockIdx.z;
    const __half* Bh = whi + (size_t)z * E * E;
    const __half* Bl = wlo + (size_t)z * E * E;
    if (z == 0)
        gemm_core(nullptr, x, Bh, Bl, nullptr, o.q, nullptr, smem, 2);
    else if (z == 1)
        gemm_core(nullptr, x, Bh, Bl, nullptr, o.kh, o.kl, smem, 1);
    else
        gemm_core(nullptr, x, Bh, Bl, nullptr, o.vh, o.vl, smem, 1);
}

__global__ __launch_bounds__(512, 1)
void gemm_out(const __half* __restrict__ p16,
              const __half* __restrict__ whi, const __half* __restrict__ wlo,
              float* __restrict__ Yf) {
    extern __shared__ char smem[];
    gemm_core(p16, nullptr, whi, wlo, Yf, nullptr, nullptr, smem, 0);
}

// ---------------- tensor-core varlen flash attention, split-K -----------------
// CTA: 128 queries of one (b,h) and a slice of its key range (NSPLIT=2).
// Q single fp16; K fp16 hi/lo; V fp16 hi/lo; P single fp16.
// Fixed-base softmax p = 2^s; purely additive partials -> combine kernel.
#define PQ 80
#define SM_KV (128 * PQ)                      // Q region: 10240
#define KVBUF (256 * PQ)                      // Khi|Klo|Vhi|Vlo, 64 rows each
#define ATTN_SMEM (SM_KV + 2 * KVBUF)         // 51200

__global__ __launch_bounds__(128, 3)
void attn_mma() {
    const int b = blockIdx.z / NSPLIT;
    const int sp = blockIdx.z % NSPLIT;
    const int h = blockIdx.y;
    const int L = g_len[b];
    const int qt = blockIdx.x * 128;
    if (qt >= L) return;

    extern __shared__ char sm[];
    const uint32_t uQh = smem_u32(sm);

    const int tid = threadIdx.x;
    const int lane = tid & 31;
    const int w = tid >> 5;
    const int wq = w * 32;
    const int g = lane >> 2;
    const int t2 = (lane & 3) * 2;

    const int pr = tid >> 2;
    const int pc = tid & 3;

    #define KV_ISSUE(k0, buf) do { \
        uint32_t dbase = uQh + SM_KV + (buf) * KVBUF; \
        _Pragma("unroll") \
        for (int i = 0; i < 8; i++) { \
            int r = pr + i * 32; \
            int region = r >> 6, rr = r & 63; \
            const __half* src = \
                (region == 0) ? g_khi : (region == 1) ? g_klo : \
                (region == 2) ? g_vhi : g_vlo; \
            cpasync16(dbase + r * PQ + pc * 16, \
                      src + ((size_t)(b * S + (k0) + rr)) * E + h * D + pc * 8); \
        } \
    } while (0)

    // key-tile range for this split
    const int ntiles = (L + 63) >> 6;
    const int chunk = (ntiles + NSPLIT - 1) / NSPLIT;
    const int t0 = sp * chunk;
    const int t1 = min(ntiles, t0 + chunk);

    // ---- stage Q tile (128 rows x 64B, single fp16) ----
    {
        int r = tid;
        size_t off = ((size_t)(b * S + qt + r)) * E + h * D;
        const uint4* sh = (const uint4*)(g_q16 + off);
        #pragma unroll
        for (int j = 0; j < 4; j++)
            *(uint4*)(sm + r * PQ + 16 * j) = sh[j];
    }
    if (t0 < t1) { KV_ISSUE(t0 * 64, t0 & 1); CP_COMMIT(); }
    __syncthreads();

    // Q fragments (kept in registers for the whole kernel)
    uint32_t qh[2][2][4];
    #pragma unroll
    for (int mi = 0; mi < 2; mi++)
        #pragma unroll
        for (int s = 0; s < 2; s++) {
            uint32_t ad = uQh + (wq + mi * 16 + (lane & 15)) * PQ
                        + (lane >> 4) * 16 + s * 32;
            ldsm4(qh[mi][s], ad);
        }

    float lsum[2][2], acc[2][4][4];
    #pragma unroll
    for (int mi = 0; mi < 2; mi++)
        #pragma unroll
        for (int hf = 0; hf < 2; hf++) lsum[mi][hf] = 0.f;
    #pragma unroll
    for (int mi = 0; mi < 2; mi++)
        #pragma unroll
        for (int nd = 0; nd < 4; nd++)
            #pragma unroll
            for (int c = 0; c < 4; c++) acc[mi][nd][c] = 0.f;

    for (int t = t0; t < t1; t++) {
        const int tn = min(64, L - t * 64);
        if (t + 1 < t1) {
            KV_ISSUE((t + 1) * 64, (t + 1) & 1);
            CP_COMMIT();
            CP_WAIT1();
        } else {
            CP_WAIT0();
        }
        __syncthreads();

        const uint32_t uK = uQh + SM_KV + (t & 1) * KVBUF;       // Khi
        const uint32_t uV = uK + 128 * PQ;                        // Vhi

        // ---- scores: S[32q x 64k] per warp; Q single x K hi/lo (2 terms) ----
        float sc[2][8][4];
        #pragma unroll
        for (int mi = 0; mi < 2; mi++)
            #pragma unroll
            for (int nj = 0; nj < 8; nj++)
                #pragma unroll
                for (int c = 0; c < 4; c++) sc[mi][nj][c] = 0.f;

        #pragma unroll
        for (int njp = 0; njp < 4; njp++) {
            uint32_t kh[2][4], kl[2][4];
            #pragma unroll
            for (int s = 0; s < 2; s++) {
                uint32_t ad = uK + (njp * 16 + (lane & 15)) * PQ
                            + (lane >> 4) * 16 + s * 32;
                ldsm4(kh[s], ad);
                ldsm4(kl[s], ad + 64 * PQ);
            }
            #pragma unroll
            for (int mi = 0; mi < 2; mi++)
                #pragma unroll
                for (int j2 = 0; j2 < 2; j2++) {
                    float* dst = sc[mi][njp * 2 + j2];
                    #pragma unroll
                    for (int s = 0; s < 2; s++) {
                        mma16816h(dst, qh[mi][s], kh[s][j2], kh[s][2 + j2]);
                        mma16816h(dst, qh[mi][s], kl[s][j2], kl[s][2 + j2]);
                    }
                }
        }

        // ---- mask tail keys ----
        if (tn < 64) {
            #pragma unroll
            for (int mi = 0; mi < 2; mi++)
                #pragma unroll
                for (int nj = 0; nj < 8; nj++)
                    #pragma unroll
                    for (int c = 0; c < 4; c++) {
                        int kc = nj * 8 + t2 + (c & 1);
                        if (kc >= tn) sc[mi][nj][c] = -1e30f;
                    }
        }

        // ---- fixed-base softmax: p = 2^s ----
        #pragma unroll
        for (int mi = 0; mi < 2; mi++)
            #pragma unroll
            for (int hf = 0; hf < 2; hf++) {
                float rowsum = 0.f;
                #pragma unroll
                for (int nj = 0; nj < 8; nj++) {
                    float p0 = ex2(sc[mi][nj][hf * 2]);
                    float p1 = ex2(sc[mi][nj][hf * 2 + 1]);
                    sc[mi][nj][hf * 2] = p0;
                    sc[mi][nj][hf * 2 + 1] = p1;
                    rowsum += p0 + p1;
                }
                rowsum += __shfl_xor_sync(0xffffffffu, rowsum, 1);
                rowsum += __shfl_xor_sync(0xffffffffu, rowsum, 2);
                lsum[mi][hf] += rowsum;
            }

        // ---- PV: O += P * V; P single fp16, V fp16 hi/lo (2-term) ----
        #pragma unroll
        for (int s = 0; s < 4; s++) {          // k16 steps
            uint32_t ph[2][4];
            #pragma unroll
            for (int mi = 0; mi < 2; mi++) {
                float* c0 = sc[mi][2 * s];
                float* c1 = sc[mi][2 * s + 1];
                ph[mi][0] = pack_f16(c0[0], c0[1]);
                ph[mi][1] = pack_f16(c0[2], c0[3]);
                ph[mi][2] = pack_f16(c1[0], c1[1]);
                ph[mi][3] = pack_f16(c1[2], c1[3]);
            }
            #pragma unroll
            for (int dp = 0; dp < 2; dp++) {   // d-octet pairs
                uint32_t ad = uV + (s * 16 + (lane & 7) + ((lane >> 3) & 1) * 8) * PQ
                            + dp * 32 + (lane >> 4) * 16;
                uint32_t vh[4], vl[4];
                ldsm4t(vh, ad);
                ldsm4t(vl, ad + 64 * PQ);
                #pragma unroll
                for (int mi = 0; mi < 2; mi++) {
                    mma16816h(acc[mi][2*dp],   ph[mi], vh[0], vh[1]);
                    mma16816h(acc[mi][2*dp],   ph[mi], vl[0], vl[1]);
                    mma16816h(acc[mi][2*dp+1], ph[mi], vh[2], vh[3]);
                    mma16816h(acc[mi][2*dp+1], ph[mi], vl[2], vl[3]);
                }
            }
        }
        __syncthreads();                       // buffer reuse safety
    }

    // ---- epilogue: raw fp32 partials (acc, lsum) to scratch ----
    #pragma unroll
    for (int mi = 0; mi < 2; mi++)
        #pragma unroll
        for (int hf = 0; hf < 2; hf++) {
            int q = qt + wq + mi * 16 + g + hf * 8;
            if (q < L) {
                size_t abase = (size_t)sp * M * E
                             + ((size_t)(b * S + q)) * E + h * D;
                #pragma unroll
                for (int nd = 0; nd < 4; nd++)
                    *(float2*)&g_pacc[abase + nd * 8 + t2] =
                        make_float2(acc[mi][nd][hf * 2], acc[mi][nd][hf * 2 + 1]);
                if ((lane & 3) == 0)
                    g_plsum[(size_t)sp * (B * S * H)
                            + ((size_t)(b * S + q)) * H + h] = lsum[mi][hf];
            }
        }
    #undef KV_ISSUE
}

// ---------------- combine: sum partials, divide, scramble-pack ----------------
__global__ __launch_bounds__(256)
void combine_kernel() {
    int idx = blockIdx.x * 256 + threadIdx.x;      // over B*S*H
    int b = idx >> 14;                             // S*H = 16384
    int rem = idx & 16383;
    int q = rem >> 3;
    int h = rem & 7;
    const int L = g_len[b];
    if (q >= L) return;

    float l = 0.f;
    #pragma unroll
    for (int sp = 0; sp < NSPLIT; sp++)
        l += g_plsum[(size_t)sp * (B * S * H) + (size_t)idx];
    float inv = 1.f / l;

    size_t abase = ((size_t)(b * S + q)) * E + h * D;
    size_t obase = (size_t)b * S * E + ((size_t)h * L + q) * D;
    #pragma unroll
    for (int d = 0; d < D; d += 4) {
        float4 a0 = *(const float4*)&g_pacc[abase + d];
        float4 a1 = *(const float4*)&g_pacc[(size_t)M * E + abase + d];
        float v0 = (a0.x + a1.x) * inv;
        float v1 = (a0.y + a1.y) * inv;
        float v2 = (a0.z + a1.z) * inv;
        float v3 = (a0.w + a1.w) * inv;
        *(uint32_t*)(g_p16 + obase + d)     = pack_f16(v0, v1);
        *(uint32_t*)(g_p16 + obase + d + 2) = pack_f16(v2, v3);
    }
}

// ---------------- launch ------------------------------------------------------
extern "C" void kernel_launch(void* const* d_in, const int* in_sizes, int n_in,
                              void* d_out, int out_size) {
    const float* x    = (const float*)d_in[0];
    const int*   mask = (const int*)  d_in[1];
    const float* Wq   = (const float*)d_in[2];
    const float* Wk   = (const float*)d_in[3];
    const float* Wv   = (const float*)d_in[4];
    const float* Wo   = (const float*)d_in[5];
    float* out = (float*)d_out;

    __half *q16, *khi, *klo, *vhi, *vlo, *p16, *whi, *wlo;
    cudaGetSymbolAddress((void**)&q16, g_q16);
    cudaGetSymbolAddress((void**)&khi, g_khi);
    cudaGetSymbolAddress((void**)&klo, g_klo);
    cudaGetSymbolAddress((void**)&vhi, g_vhi);
    cudaGetSymbolAddress((void**)&vlo, g_vlo);
    cudaGetSymbolAddress((void**)&p16, g_p16);
    cudaGetSymbolAddress((void**)&whi, g_whi);
    cudaGetSymbolAddress((void**)&wlo, g_wlo);

    cudaFuncSetAttribute(gemm_qkv, cudaFuncAttributeMaxDynamicSharedMemorySize,
                         GEMM_SMEM);
    cudaFuncSetAttribute(gemm_out, cudaFuncAttributeMaxDynamicSharedMemorySize,
                         GEMM_SMEM);
    cudaFuncSetAttribute(attn_mma, cudaFuncAttributeMaxDynamicSharedMemorySize,
                         ATTN_SMEM);

    len_kernel<<<B, 256>>>(mask);
    cudaMemsetAsync(p16, 0, (size_t)M * E * sizeof(__half), 0);

    decompw_kernel<<<dim3(E*E/4/256, 4), 256>>>(Wq, Wk, Wv, Wo, whi, wlo);

    QKVOuts o = { q16, khi, klo, vhi, vlo };
    dim3 gq(M / 128, E / 128, 3);
    gemm_qkv<<<gq, 512, GEMM_SMEM>>>(x, whi, wlo, o);

    dim3 ga(S / 128, H, B * NSPLIT);
    attn_mma<<<ga, 128, ATTN_SMEM>>>();
    combine_kernel<<<(B*S*H)/256, 256>>>();

    dim3 gg(M / 128, E / 128);
    gemm_out<<<gg, 512, GEMM_SMEM>>>(p16, whi + 3*E*E, wlo + 3*E*E, out);
}

// round 15
// speedup vs baseline: 1.0590x; 1.0590x over previous
#include <cuda_runtime.h>
#include <cuda_fp16.h>
#include <stdint.h>

#define B 4
#define S 2048
#define E 256
#define H 8
#define D 32
#define M (B*S)
#define NSPLIT 2
// SCALE * log2(e), folded into Wq at decomposition time
#define CEXP (0.17677669529663687f * 1.44269504088896341f)

// ---------------- scratch (device globals; no allocation allowed) ----------
static __device__ __align__(16) __half g_q16[M*E];
static __device__ __align__(16) __half g_khi[M*E];
static __device__ __align__(16) __half g_klo[M*E];
static __device__ __align__(16) __half g_vhi[M*E];
static __device__ __align__(16) __half g_vlo[M*E];
static __device__ __align__(16) __half g_whi[4*E*E];
static __device__ __align__(16) __half g_wlo[4*E*E];
static __device__ __align__(16) float g_pacc[NSPLIT*M*E];
static __device__ __align__(16) float g_plsum[NSPLIT*B*S*H];
static __device__ int g_len[B];

// ---------------- helpers ----------------------------------------------------
__device__ __forceinline__ uint32_t smem_u32(const void* p) {
    uint32_t a;
    asm("{ .reg .u64 t; cvta.to.shared.u64 t, %1; cvt.u32.u64 %0, t; }"
        : "=r"(a) : "l"(p));
    return a;
}

__device__ __forceinline__ void ldsm4(uint32_t* r, uint32_t addr) {
    asm volatile("ldmatrix.sync.aligned.m8n8.x4.shared.b16 {%0,%1,%2,%3}, [%4];"
                 : "=r"(r[0]), "=r"(r[1]), "=r"(r[2]), "=r"(r[3]) : "r"(addr));
}

__device__ __forceinline__ void ldsm4t(uint32_t* r, uint32_t addr) {
    asm volatile("ldmatrix.sync.aligned.m8n8.x4.trans.shared.b16 {%0,%1,%2,%3}, [%4];"
                 : "=r"(r[0]), "=r"(r[1]), "=r"(r[2]), "=r"(r[3]) : "r"(addr));
}

// fp16 MMA
__device__ __forceinline__ void mma16816h(float* d, const uint32_t* a,
                                          uint32_t b0, uint32_t b1) {
    asm volatile(
        "mma.sync.aligned.m16n8k16.row.col.f32.f16.f16.f32 "
        "{%0,%1,%2,%3}, {%4,%5,%6,%7}, {%8,%9}, {%0,%1,%2,%3};"
        : "+f"(d[0]), "+f"(d[1]), "+f"(d[2]), "+f"(d[3])
        : "r"(a[0]), "r"(a[1]), "r"(a[2]), "r"(a[3]), "r"(b0), "r"(b1));
}

__device__ __forceinline__ float ex2(float x) {
    float y;
    asm("ex2.approx.ftz.f32 %0, %1;" : "=f"(y) : "f"(x));
    return y;
}

__device__ __forceinline__ void cpasync16(uint32_t saddr, const void* g) {
    asm volatile("cp.async.cg.shared.global [%0], [%1], 16;"
                 :: "r"(saddr), "l"(g));
}
#define CP_COMMIT() asm volatile("cp.async.commit_group;" ::: "memory")
#define CP_WAIT0()  asm volatile("cp.async.wait_group 0;" ::: "memory")
#define CP_WAIT1()  asm volatile("cp.async.wait_group 1;" ::: "memory")

// fp16 pack helpers
__device__ __forceinline__ uint32_t pack_f16(float a, float b) {
    uint32_t h;
    asm("cvt.rn.f16x2.f32 %0, %1, %2;" : "=r"(h) : "f"(b), "f"(a));
    return h;
}
__device__ __forceinline__ void split_pair_f16(float a, float b,
                                               uint32_t& hi, uint32_t& lo) {
    uint32_t h = pack_f16(a, b);
    float ha, hb;
    asm("{\n .reg .f16 x, y;\n mov.b32 {x, y}, %2;\n"
        " cvt.f32.f16 %0, x;\n cvt.f32.f16 %1, y;\n}"
        : "=f"(ha), "=f"(hb) : "r"(h));
    lo = pack_f16(a - ha, b - hb);
    hi = h;
}

// load 8 fp32 and pack to 8 fp16 (16B payload)
__device__ __forceinline__ float4 ld_cvt8(const float* p) {
    float4 a = *(const float4*)p;
    float4 b = *(const float4*)(p + 4);
    float4 r;
    ((uint32_t*)&r)[0] = pack_f16(a.x, a.y);
    ((uint32_t*)&r)[1] = pack_f16(a.z, a.w);
    ((uint32_t*)&r)[2] = pack_f16(b.x, b.y);
    ((uint32_t*)&r)[3] = pack_f16(b.z, b.w);
    return r;
}

// combine split-K attention partials + scramble-map, pack 8 fp16.
// gemm_out A row (b,s) col kcol: scrambled flat = s*E+kcol = h*L*D + q*D + d.
__device__ __forceinline__ float4 ld_comb8(int row, int kcol) {
    int b = row >> 11;                 // S = 2048
    int s = row & (S - 1);
    int L = g_len[b];
    int flat = s * E + kcol;
    if (flat >= L * E) return make_float4(0.f, 0.f, 0.f, 0.f);
    int h = flat / (L * D);
    int rem = flat - h * (L * D);
    int q = rem >> 5;                  // D = 32
    int d = rem & 31;                  // 8-aligned (kcol is)
    size_t abase = ((size_t)(b * S + q)) * E + h * D + d;
    float4 a0 = *(const float4*)&g_pacc[abase];
    float4 b0 = *(const float4*)&g_pacc[abase + 4];
    float4 a1 = *(const float4*)&g_pacc[(size_t)M * E + abase];
    float4 b1 = *(const float4*)&g_pacc[(size_t)M * E + abase + 4];
    int li = (b * S + q) * H + h;
    float inv = 1.f / (g_plsum[li] + g_plsum[B * S * H + li]);
    float4 r;
    ((uint32_t*)&r)[0] = pack_f16((a0.x + a1.x) * inv, (a0.y + a1.y) * inv);
    ((uint32_t*)&r)[1] = pack_f16((a0.z + a1.z) * inv, (a0.w + a1.w) * inv);
    ((uint32_t*)&r)[2] = pack_f16((b0.x + b1.x) * inv, (b0.y + b1.y) * inv);
    ((uint32_t*)&r)[3] = pack_f16((b0.z + b1.z) * inv, (b0.w + b1.w) * inv);
    return r;
}

// ---------------- lengths ----------------------------------------------------
__global__ void len_kernel(const int* __restrict__ mask) {
    int b = blockIdx.x;
    int t = threadIdx.x;
    int s = 0;
    for (int i = t; i < S; i += 256) s += mask[b*S + i];
    __shared__ int sh[256];
    sh[t] = s;
    __syncthreads();
    for (int o = 128; o > 0; o >>= 1) {
        if (t < o) sh[t] += sh[t + o];
        __syncthreads();
    }
    if (t == 0) g_len[b] = sh[0];
}

// all 4 weight matrices, fp16 hi/lo; Wq (y==0) pre-scaled by CEXP
__global__ __launch_bounds__(256)
void decompw_kernel(const float* __restrict__ w0, const float* __restrict__ w1,
                    const float* __restrict__ w2, const float* __restrict__ w3,
                    __half* __restrict__ hi, __half* __restrict__ lo) {
    int m = blockIdx.y;
    const float* src = (m == 0) ? w0 : (m == 1) ? w1 : (m == 2) ? w2 : w3;
    float sc = (m == 0) ? CEXP : 1.0f;
    int i = blockIdx.x * 256 + threadIdx.x;           // over E*E/4
    float4 v = ((const float4*)src)[i];
    float f[4] = {v.x * sc, v.y * sc, v.z * sc, v.w * sc};
    size_t base = (size_t)m * E * E + 4 * (size_t)i;
    uint32_t h0, l0, h1, l1;
    split_pair_f16(f[0], f[1], h0, l0);
    split_pair_f16(f[2], f[3], h1, l1);
    *(uint32_t*)(hi + base) = h0;  *(uint32_t*)(hi + base + 2) = h1;
    *(uint32_t*)(lo + base) = l0;  *(uint32_t*)(lo + base + 2) = l1;
}

// ---------------- fp16x2 GEMM core: Y[m,n] = sum_k X[m,k] W[n,k] -------------
// A single fp16 (direct, fp32-converted, or combined from attention partials),
// W fp16 hi/lo (2-term). CTA 128x128, 512 threads, warp 32x32, K chunks of 64
// double-buffered via register prefetch.
#define GPITCH 144
#define GCHUNKB (128 * GPITCH)
#define GBUFB (3 * GCHUNKB)                    // A | Bh | Bl
#define GEMM_SMEM (2 * GBUFB)                  // 110592

// AMODE: 0 = __half direct, 1 = fp32 convert, 2 = split-K combine
// OMODE: 0 = fp32 out, 1 = fp16 hi/lo, 2 = fp16 single
template<int AMODE, int OMODE>
__device__ __forceinline__ void gemm_core(
    const __half* __restrict__ Ah, const float* __restrict__ Af,
    const __half* __restrict__ Bhi, const __half* __restrict__ Blo,
    float* __restrict__ Yf,
    __half* __restrict__ Yhi, __half* __restrict__ Ylo,
    char* smem) {
    const int bm = blockIdx.x * 128;
    const int bn = blockIdx.y * 128;
    const int tid = threadIdx.x;
    const int lane = tid & 31;
    const int wid = tid >> 5;
    const int wm = (wid & 3) * 32;
    const int wn = (wid >> 2) * 32;
    const uint32_t base = smem_u32(smem);

    float acc[2][4][4];
    #pragma unroll
    for (int mi = 0; mi < 2; mi++)
        #pragma unroll
        for (int ni = 0; ni < 4; ni++)
            #pragma unroll
            for (int k = 0; k < 4; k++) acc[mi][ni][k] = 0.f;

    const int a_row = lane & 15;
    const int a_kb  = (lane >> 4) * 16;
    const int pr0 = tid >> 3, pc0 = tid & 7;
    const int pr1 = (tid + 512) >> 3, pc1 = (tid + 512) & 7;

    float4 pf[6];
    #define PFLOAD(k0) do { \
        if (AMODE == 2) { \
            pf[0] = ld_comb8(bm + pr0, (k0) + pc0 * 8); \
            pf[3] = ld_comb8(bm + pr1, (k0) + pc1 * 8); \
        } else if (AMODE == 1) { \
            pf[0] = ld_cvt8(Af + (size_t)(bm + pr0) * E + (k0) + pc0 * 8); \
            pf[3] = ld_cvt8(Af + (size_t)(bm + pr1) * E + (k0) + pc1 * 8); \
        } else { \
            pf[0] = *(const float4*)(Ah + (size_t)(bm + pr0) * E + (k0) + pc0 * 8); \
            pf[3] = *(const float4*)(Ah + (size_t)(bm + pr1) * E + (k0) + pc1 * 8); \
        } \
        size_t g0 = (size_t)pr0 * E + (k0) + pc0 * 8; \
        size_t g1 = (size_t)pr1 * E + (k0) + pc1 * 8; \
        pf[1] = *(const float4*)(Bhi + (size_t)bn * E + g0); \
        pf[2] = *(const float4*)(Blo + (size_t)bn * E + g0); \
        pf[4] = *(const float4*)(Bhi + (size_t)bn * E + g1); \
        pf[5] = *(const float4*)(Blo + (size_t)bn * E + g1); \
    } while (0)
    #define PFSTORE(buf) do { \
        char* bp = smem + (buf) * GBUFB; \
        int s0 = pr0 * GPITCH + pc0 * 16; \
        int s1 = pr1 * GPITCH + pc1 * 16; \
        *(float4*)(bp + s0)               = pf[0]; \
        *(float4*)(bp + GCHUNKB + s0)     = pf[1]; \
        *(float4*)(bp + 2 * GCHUNKB + s0) = pf[2]; \
        *(float4*)(bp + s1)               = pf[3]; \
        *(float4*)(bp + GCHUNKB + s1)     = pf[4]; \
        *(float4*)(bp + 2 * GCHUNKB + s1) = pf[5]; \
    } while (0)

    PFLOAD(0);
    PFSTORE(0);
    __syncthreads();

    for (int kc = 0; kc < 4; kc++) {
        if (kc < 3) PFLOAD((kc + 1) * 64);
        const uint32_t uA = base + (kc & 1) * GBUFB;
        const uint32_t uB = uA + GCHUNKB;

        #pragma unroll
        for (int ks = 0; ks < 4; ks++) {
            const int kb = ks * 32;
            uint32_t a[2][4], bhi[4][2], blo[4][2];
            #pragma unroll
            for (int mi = 0; mi < 2; mi++) {
                uint32_t off = (uint32_t)((wm + mi * 16 + a_row) * GPITCH + kb + a_kb);
                ldsm4(a[mi], uA + off);
            }
            #pragma unroll
            for (int np = 0; np < 2; np++) {
                uint32_t off = (uint32_t)((wn + np * 16 + a_row) * GPITCH + kb + a_kb);
                uint32_t th[4], tl[4];
                ldsm4(th, uB + off);
                ldsm4(tl, uB + GCHUNKB + off);
                bhi[np*2][0] = th[0]; bhi[np*2][1] = th[2];
                bhi[np*2+1][0] = th[1]; bhi[np*2+1][1] = th[3];
                blo[np*2][0] = tl[0]; blo[np*2][1] = tl[2];
                blo[np*2+1][0] = tl[1]; blo[np*2+1][1] = tl[3];
            }
            #pragma unroll
            for (int mi = 0; mi < 2; mi++)
                #pragma unroll
                for (int ni = 0; ni < 4; ni++) {
                    mma16816h(acc[mi][ni], a[mi], bhi[ni][0], bhi[ni][1]);
                    mma16816h(acc[mi][ni], a[mi], blo[ni][0], blo[ni][1]);
                }
        }
        if (kc < 3) {
            PFSTORE((kc + 1) & 1);
            __syncthreads();
        }
    }

    const int g = lane >> 2;
    const int t2 = (lane & 3) * 2;
    #pragma unroll
    for (int mi = 0; mi < 2; mi++)
        #pragma unroll
        for (int ni = 0; ni < 4; ni++) {
            int row = bm + wm + mi * 16 + g;
            int col = bn + wn + ni * 8 + t2;
            float* ac = acc[mi][ni];
            if (OMODE == 0) {
                *(float2*)&Yf[(size_t)row * E + col] = make_float2(ac[0], ac[1]);
                *(float2*)&Yf[(size_t)(row + 8) * E + col] = make_float2(ac[2], ac[3]);
            } else if (OMODE == 2) {
                *(uint32_t*)(Yhi + (size_t)row * E + col) = pack_f16(ac[0], ac[1]);
                *(uint32_t*)(Yhi + (size_t)(row + 8) * E + col) = pack_f16(ac[2], ac[3]);
            } else {
                uint32_t h0, l0, h1, l1;
                split_pair_f16(ac[0], ac[1], h0, l0);
                split_pair_f16(ac[2], ac[3], h1, l1);
                *(uint32_t*)(Yhi + (size_t)row * E + col) = h0;
                *(uint32_t*)(Ylo + (size_t)row * E + col) = l0;
                *(uint32_t*)(Yhi + (size_t)(row + 8) * E + col) = h1;
                *(uint32_t*)(Ylo + (size_t)(row + 8) * E + col) = l1;
            }
        }
    #undef PFLOAD
    #undef PFSTORE
}

struct QKVOuts {
    __half *q, *kh, *kl, *vh, *vl;
};

// fused Q/K/V projections from fp32 x: z=0 Q (fp16), z=1 K (hi/lo), z=2 V (hi/lo)
__global__ __launch_bounds__(512, 1)
void gemm_qkv(const float* __restrict__ x,
              const __half* __restrict__ whi, const __half* __restrict__ wlo,
              QKVOuts o) {
    extern __shared__ char smem[];
    const int z = blockIdx.z;
    const __half* Bh = whi + (size_t)z * E * E;
    const __half* Bl = wlo + (size_t)z * E * E;
    if (z == 0)
        gemm_core<1, 2>(nullptr, x, Bh, Bl, nullptr, o.q, nullptr, smem);
    else if (z == 1)
        gemm_core<1, 1>(nullptr, x, Bh, Bl, nullptr, o.kh, o.kl, smem);
    else
        gemm_core<1, 1>(nullptr, x, Bh, Bl, nullptr, o.vh, o.vl, smem);
}

// output GEMM with fused split-K combine + scramble on the A side
__global__ __launch_bounds__(512, 1)
void gemm_out(const __half* __restrict__ whi, const __half* __restrict__ wlo,
              float* __restrict__ Yf) {
    extern __shared__ char smem[];
    gemm_core<2, 0>(nullptr, nullptr, whi, wlo, Yf, nullptr, nullptr, smem);
}

// ---------------- tensor-core varlen flash attention, split-K -----------------
// CTA: 128 queries of one (b,h) and a slice of its key range (NSPLIT=2).
// Q single fp16; K fp16 hi/lo; V fp16 hi/lo; P single fp16.
// Fixed-base softmax p = 2^s; purely additive partials.
#define PQ 80
#define SM_KV (128 * PQ)                      // Q region: 10240
#define KVBUF (256 * PQ)                      // Khi|Klo|Vhi|Vlo, 64 rows each
#define ATTN_SMEM (SM_KV + 2 * KVBUF)         // 51200

__global__ __launch_bounds__(128, 2)
void attn_mma() {
    const int b = blockIdx.z / NSPLIT;
    const int sp = blockIdx.z % NSPLIT;
    const int h = blockIdx.y;
    const int L = g_len[b];
    const int qt = blockIdx.x * 128;
    if (qt >= L) return;

    extern __shared__ char sm[];
    const uint32_t uQh = smem_u32(sm);

    const int tid = threadIdx.x;
    const int lane = tid & 31;
    const int w = tid >> 5;
    const int wq = w * 32;
    const int g = lane >> 2;
    const int t2 = (lane & 3) * 2;

    const int pr = tid >> 2;
    const int pc = tid & 3;

    #define KV_ISSUE(k0, buf) do { \
        uint32_t dbase = uQh + SM_KV + (buf) * KVBUF; \
        _Pragma("unroll") \
        for (int i = 0; i < 8; i++) { \
            int r = pr + i * 32; \
            int region = r >> 6, rr = r & 63; \
            const __half* src = \
                (region == 0) ? g_khi : (region == 1) ? g_klo : \
                (region == 2) ? g_vhi : g_vlo; \
            cpasync16(dbase + r * PQ + pc * 16, \
                      src + ((size_t)(b * S + (k0) + rr)) * E + h * D + pc * 8); \
        } \
    } while (0)

    // key-tile range for this split
    const int ntiles = (L + 63) >> 6;
    const int chunk = (ntiles + NSPLIT - 1) / NSPLIT;
    const int t0 = sp * chunk;
    const int t1 = min(ntiles, t0 + chunk);

    // ---- stage Q tile (128 rows x 64B, single fp16) ----
    {
        int r = tid;
        size_t off = ((size_t)(b * S + qt + r)) * E + h * D;
        const uint4* sh = (const uint4*)(g_q16 + off);
        #pragma unroll
        for (int j = 0; j < 4; j++)
            *(uint4*)(sm + r * PQ + 16 * j) = sh[j];
    }
    if (t0 < t1) { KV_ISSUE(t0 * 64, t0 & 1); CP_COMMIT(); }
    __syncthreads();

    // Q fragments (kept in registers for the whole kernel)
    uint32_t qh[2][2][4];
    #pragma unroll
    for (int mi = 0; mi < 2; mi++)
        #pragma unroll
        for (int s = 0; s < 2; s++) {
            uint32_t ad = uQh + (wq + mi * 16 + (lane & 15)) * PQ
                        + (lane >> 4) * 16 + s * 32;
            ldsm4(qh[mi][s], ad);
        }

    float lsum[2][2], acc[2][4][4];
    #pragma unroll
    for (int mi = 0; mi < 2; mi++)
        #pragma unroll
        for (int hf = 0; hf < 2; hf++) lsum[mi][hf] = 0.f;
    #pragma unroll
    for (int mi = 0; mi < 2; mi++)
        #pragma unroll
        for (int nd = 0; nd < 4; nd++)
            #pragma unroll
            for (int c = 0; c < 4; c++) acc[mi][nd][c] = 0.f;

    for (int t = t0; t < t1; t++) {
        const int tn = min(64, L - t * 64);
        if (t + 1 < t1) {
            KV_ISSUE((t + 1) * 64, (t + 1) & 1);
            CP_COMMIT();
            CP_WAIT1();
        } else {
            CP_WAIT0();
        }
        __syncthreads();

        const uint32_t uK = uQh + SM_KV + (t & 1) * KVBUF;       // Khi
        const uint32_t uV = uK + 128 * PQ;                        // Vhi

        // ---- scores: S[32q x 64k] per warp; Q single x K hi/lo (2 terms) ----
        float sc[2][8][4];
        #pragma unroll
        for (int mi = 0; mi < 2; mi++)
            #pragma unroll
            for (int nj = 0; nj < 8; nj++)
                #pragma unroll
                for (int c = 0; c < 4; c++) sc[mi][nj][c] = 0.f;

        #pragma unroll
        for (int njp = 0; njp < 4; njp++) {
            uint32_t kh[2][4], kl[2][4];
            #pragma unroll
            for (int s = 0; s < 2; s++) {
                uint32_t ad = uK + (njp * 16 + (lane & 15)) * PQ
                            + (lane >> 4) * 16 + s * 32;
                ldsm4(kh[s], ad);
                ldsm4(kl[s], ad + 64 * PQ);
            }
            #pragma unroll
            for (int mi = 0; mi < 2; mi++)
                #pragma unroll
                for (int j2 = 0; j2 < 2; j2++) {
                    float* dst = sc[mi][njp * 2 + j2];
                    #pragma unroll
                    for (int s = 0; s < 2; s++) {
                        mma16816h(dst, qh[mi][s], kh[s][j2], kh[s][2 + j2]);
                        mma16816h(dst, qh[mi][s], kl[s][j2], kl[s][2 + j2]);
                    }
                }
        }

        // ---- mask tail keys ----
        if (tn < 64) {
            #pragma unroll
            for (int mi = 0; mi < 2; mi++)
                #pragma unroll
                for (int nj = 0; nj < 8; nj++)
                    #pragma unroll
                    for (int c = 0; c < 4; c++) {
                        int kc = nj * 8 + t2 + (c & 1);
                        if (kc >= tn) sc[mi][nj][c] = -1e30f;
                    }
        }

        // ---- fixed-base softmax: p = 2^s ----
        #pragma unroll
        for (int mi = 0; mi < 2; mi++)
            #pragma unroll
            for (int hf = 0; hf < 2; hf++) {
                float rowsum = 0.f;
                #pragma unroll
                for (int nj = 0; nj < 8; nj++) {
                    float p0 = ex2(sc[mi][nj][hf * 2]);
                    float p1 = ex2(sc[mi][nj][hf * 2 + 1]);
                    sc[mi][nj][hf * 2] = p0;
                    sc[mi][nj][hf * 2 + 1] = p1;
                    rowsum += p0 + p1;
                }
                rowsum += __shfl_xor_sync(0xffffffffu, rowsum, 1);
                rowsum += __shfl_xor_sync(0xffffffffu, rowsum, 2);
                lsum[mi][hf] += rowsum;
            }

        // ---- PV: O += P * V; P single fp16, V fp16 hi/lo (2-term) ----
        #pragma unroll
        for (int s = 0; s < 4; s++) {          // k16 steps
            uint32_t ph[2][4];
            #pragma unroll
            for (int mi = 0; mi < 2; mi++) {
                float* c0 = sc[mi][2 * s];
                float* c1 = sc[mi][2 * s + 1];
                ph[mi][0] = pack_f16(c0[0], c0[1]);
                ph[mi][1] = pack_f16(c0[2], c0[3]);
                ph[mi][2] = pack_f16(c1[0], c1[1]);
                ph[mi][3] = pack_f16(c1[2], c1[3]);
            }
            #pragma unroll
            for (int dp = 0; dp < 2; dp++) {   // d-octet pairs
                uint32_t ad = uV + (s * 16 + (lane & 7) + ((lane >> 3) & 1) * 8) * PQ
                            + dp * 32 + (lane >> 4) * 16;
                uint32_t vh[4], vl[4];
                ldsm4t(vh, ad);
                ldsm4t(vl, ad + 64 * PQ);
                #pragma unroll
                for (int mi = 0; mi < 2; mi++) {
                    mma16816h(acc[mi][2*dp],   ph[mi], vh[0], vh[1]);
                    mma16816h(acc[mi][2*dp],   ph[mi], vl[0], vl[1]);
                    mma16816h(acc[mi][2*dp+1], ph[mi], vh[2], vh[3]);
                    mma16816h(acc[mi][2*dp+1], ph[mi], vl[2], vl[3]);
                }
            }
        }
        __syncthreads();                       // buffer reuse safety
    }

    // ---- epilogue: raw fp32 partials (acc, lsum) to scratch ----
    #pragma unroll
    for (int mi = 0; mi < 2; mi++)
        #pragma unroll
        for (int hf = 0; hf < 2; hf++) {
            int q = qt + wq + mi * 16 + g + hf * 8;
            if (q < L) {
                size_t abase = (size_t)sp * M * E
                             + ((size_t)(b * S + q)) * E + h * D;
                #pragma unroll
                for (int nd = 0; nd < 4; nd++)
                    *(float2*)&g_pacc[abase + nd * 8 + t2] =
                        make_float2(acc[mi][nd][hf * 2], acc[mi][nd][hf * 2 + 1]);
                if ((lane & 3) == 0)
                    g_plsum[(size_t)sp * (B * S * H)
                            + ((size_t)(b * S + q)) * H + h] = lsum[mi][hf];
            }
        }
    #undef KV_ISSUE
}

// ---------------- launch ------------------------------------------------------
extern "C" void kernel_launch(void* const* d_in, const int* in_sizes, int n_in,
                              void* d_out, int out_size) {
    const float* x    = (const float*)d_in[0];
    const int*   mask = (const int*)  d_in[1];
    const float* Wq   = (const float*)d_in[2];
    const float* Wk   = (const float*)d_in[3];
    const float* Wv   = (const float*)d_in[4];
    const float* Wo   = (const float*)d_in[5];
    float* out = (float*)d_out;

    __half *q16, *khi, *klo, *vhi, *vlo, *whi, *wlo;
    cudaGetSymbolAddress((void**)&q16, g_q16);
    cudaGetSymbolAddress((void**)&khi, g_khi);
    cudaGetSymbolAddress((void**)&klo, g_klo);
    cudaGetSymbolAddress((void**)&vhi, g_vhi);
    cudaGetSymbolAddress((void**)&vlo, g_vlo);
    cudaGetSymbolAddress((void**)&whi, g_whi);
    cudaGetSymbolAddress((void**)&wlo, g_wlo);

    cudaFuncSetAttribute(gemm_qkv, cudaFuncAttributeMaxDynamicSharedMemorySize,
                         GEMM_SMEM);
    cudaFuncSetAttribute(gemm_out, cudaFuncAttributeMaxDynamicSharedMemorySize,
                         GEMM_SMEM);
    cudaFuncSetAttribute(attn_mma, cudaFuncAttributeMaxDynamicSharedMemorySize,
                         ATTN_SMEM);

    len_kernel<<<B, 256>>>(mask);
    decompw_kernel<<<dim3(E*E/4/256, 4), 256>>>(Wq, Wk, Wv, Wo, whi, wlo);

    QKVOuts o = { q16, khi, klo, vhi, vlo };
    dim3 gq(M / 128, E / 128, 3);
    gemm_qkv<<<gq, 512, GEMM_SMEM>>>(x, whi, wlo, o);

    dim3 ga(S / 128, H, B * NSPLIT);
    attn_mma<<<ga, 128, ATTN_SMEM>>>();

    dim3 gg(M / 128, E / 128);
    gemm_out<<<gg, 512, GEMM_SMEM>>>(whi + 3*E*E, wlo + 3*E*E, out);
}

// round 16
// speedup vs baseline: 1.1684x; 1.1033x over previous
#include <cuda_runtime.h>
#include <cuda_fp16.h>
#include <stdint.h>

#define B 4
#define S 2048
#define E 256
#define H 8
#define D 32
#define M (B*S)
#define NSPLIT 2
// SCALE * log2(e), folded into Wq at decomposition time
#define CEXP (0.17677669529663687f * 1.44269504088896341f)

// ---------------- scratch (device globals; no allocation allowed) ----------
static __device__ __align__(16) __half g_q16[M*E];
static __device__ __align__(16) __half g_khi[M*E];
static __device__ __align__(16) __half g_klo[M*E];
static __device__ __align__(16) __half g_v16[M*E];
static __device__ __align__(16) __half g_whi[4*E*E];
static __device__ __align__(16) __half g_wlo[4*E*E];
static __device__ __align__(16) float g_pacc[NSPLIT*M*E];
static __device__ __align__(16) float g_plsum[NSPLIT*B*S*H];
static __device__ int g_len[B];

// ---------------- helpers ----------------------------------------------------
__device__ __forceinline__ uint32_t smem_u32(const void* p) {
    uint32_t a;
    asm("{ .reg .u64 t; cvta.to.shared.u64 t, %1; cvt.u32.u64 %0, t; }"
        : "=r"(a) : "l"(p));
    return a;
}

__device__ __forceinline__ void ldsm4(uint32_t* r, uint32_t addr) {
    asm volatile("ldmatrix.sync.aligned.m8n8.x4.shared.b16 {%0,%1,%2,%3}, [%4];"
                 : "=r"(r[0]), "=r"(r[1]), "=r"(r[2]), "=r"(r[3]) : "r"(addr));
}

__device__ __forceinline__ void ldsm4t(uint32_t* r, uint32_t addr) {
    asm volatile("ldmatrix.sync.aligned.m8n8.x4.trans.shared.b16 {%0,%1,%2,%3}, [%4];"
                 : "=r"(r[0]), "=r"(r[1]), "=r"(r[2]), "=r"(r[3]) : "r"(addr));
}

// fp16 MMA
__device__ __forceinline__ void mma16816h(float* d, const uint32_t* a,
                                          uint32_t b0, uint32_t b1) {
    asm volatile(
        "mma.sync.aligned.m16n8k16.row.col.f32.f16.f16.f32 "
        "{%0,%1,%2,%3}, {%4,%5,%6,%7}, {%8,%9}, {%0,%1,%2,%3};"
        : "+f"(d[0]), "+f"(d[1]), "+f"(d[2]), "+f"(d[3])
        : "r"(a[0]), "r"(a[1]), "r"(a[2]), "r"(a[3]), "r"(b0), "r"(b1));
}

__device__ __forceinline__ float ex2(float x) {
    float y;
    asm("ex2.approx.ftz.f32 %0, %1;" : "=f"(y) : "f"(x));
    return y;
}

__device__ __forceinline__ void cpasync16(uint32_t saddr, const void* g) {
    asm volatile("cp.async.cg.shared.global [%0], [%1], 16;"
                 :: "r"(saddr), "l"(g));
}
#define CP_COMMIT() asm volatile("cp.async.commit_group;" ::: "memory")
#define CP_WAIT0()  asm volatile("cp.async.wait_group 0;" ::: "memory")
#define CP_WAIT1()  asm volatile("cp.async.wait_group 1;" ::: "memory")

// fp16 pack helpers
__device__ __forceinline__ uint32_t pack_f16(float a, float b) {
    uint32_t h;
    asm("cvt.rn.f16x2.f32 %0, %1, %2;" : "=r"(h) : "f"(b), "f"(a));
    return h;
}
__device__ __forceinline__ void split_pair_f16(float a, float b,
                                               uint32_t& hi, uint32_t& lo) {
    uint32_t h = pack_f16(a, b);
    float ha, hb;
    asm("{\n .reg .f16 x, y;\n mov.b32 {x, y}, %2;\n"
        " cvt.f32.f16 %0, x;\n cvt.f32.f16 %1, y;\n}"
        : "=f"(ha), "=f"(hb) : "r"(h));
    lo = pack_f16(a - ha, b - hb);
    hi = h;
}

// load 8 fp32 and pack to 8 fp16 (16B payload)
__device__ __forceinline__ float4 ld_cvt8(const float* p) {
    float4 a = *(const float4*)p;
    float4 b = *(const float4*)(p + 4);
    float4 r;
    ((uint32_t*)&r)[0] = pack_f16(a.x, a.y);
    ((uint32_t*)&r)[1] = pack_f16(a.z, a.w);
    ((uint32_t*)&r)[2] = pack_f16(b.x, b.y);
    ((uint32_t*)&r)[3] = pack_f16(b.z, b.w);
    return r;
}

// combine split-K attention partials + scramble-map, pack 8 fp16.
// gemm_out A row (b,s) col kcol: scrambled flat = s*E+kcol = h*L*D + q*D + d.
__device__ __forceinline__ float4 ld_comb8(int row, int kcol) {
    int b = row >> 11;                 // S = 2048
    int s = row & (S - 1);
    int L = g_len[b];
    int flat = s * E + kcol;
    if (flat >= L * E) return make_float4(0.f, 0.f, 0.f, 0.f);
    int h = flat / (L * D);
    int rem = flat - h * (L * D);
    int q = rem >> 5;                  // D = 32
    int d = rem & 31;                  // 8-aligned (kcol is)
    size_t abase = ((size_t)(b * S + q)) * E + h * D + d;
    float4 a0 = *(const float4*)&g_pacc[abase];
    float4 b0 = *(const float4*)&g_pacc[abase + 4];
    float4 a1 = *(const float4*)&g_pacc[(size_t)M * E + abase];
    float4 b1 = *(const float4*)&g_pacc[(size_t)M * E + abase + 4];
    int li = (b * S + q) * H + h;
    float inv = 1.f / (g_plsum[li] + g_plsum[B * S * H + li]);
    float4 r;
    ((uint32_t*)&r)[0] = pack_f16((a0.x + a1.x) * inv, (a0.y + a1.y) * inv);
    ((uint32_t*)&r)[1] = pack_f16((a0.z + a1.z) * inv, (a0.w + a1.w) * inv);
    ((uint32_t*)&r)[2] = pack_f16((b0.x + b1.x) * inv, (b0.y + b1.y) * inv);
    ((uint32_t*)&r)[3] = pack_f16((b0.z + b1.z) * inv, (b0.w + b1.w) * inv);
    return r;
}

// ---------------- lengths ----------------------------------------------------
__global__ void len_kernel(const int* __restrict__ mask) {
    int b = blockIdx.x;
    int t = threadIdx.x;
    int s = 0;
    for (int i = t; i < S; i += 256) s += mask[b*S + i];
    __shared__ int sh[256];
    sh[t] = s;
    __syncthreads();
    for (int o = 128; o > 0; o >>= 1) {
        if (t < o) sh[t] += sh[t + o];
        __syncthreads();
    }
    if (t == 0) g_len[b] = sh[0];
}

// all 4 weight matrices, fp16 hi/lo; Wq (y==0) pre-scaled by CEXP
__global__ __launch_bounds__(256)
void decompw_kernel(const float* __restrict__ w0, const float* __restrict__ w1,
                    const float* __restrict__ w2, const float* __restrict__ w3,
                    __half* __restrict__ hi, __half* __restrict__ lo) {
    int m = blockIdx.y;
    const float* src = (m == 0) ? w0 : (m == 1) ? w1 : (m == 2) ? w2 : w3;
    float sc = (m == 0) ? CEXP : 1.0f;
    int i = blockIdx.x * 256 + threadIdx.x;           // over E*E/4
    float4 v = ((const float4*)src)[i];
    float f[4] = {v.x * sc, v.y * sc, v.z * sc, v.w * sc};
    size_t base = (size_t)m * E * E + 4 * (size_t)i;
    uint32_t h0, l0, h1, l1;
    split_pair_f16(f[0], f[1], h0, l0);
    split_pair_f16(f[2], f[3], h1, l1);
    *(uint32_t*)(hi + base) = h0;  *(uint32_t*)(hi + base + 2) = h1;
    *(uint32_t*)(lo + base) = l0;  *(uint32_t*)(lo + base + 2) = l1;
}

// ---------------- fp16x2 GEMM core: Y[m,n] = sum_k X[m,k] W[n,k] -------------
// A single fp16 (fp32-converted or combined from attention partials),
// W fp16 hi/lo (2-term). CTA 128x128, 512 threads, warp 32x32, K chunks of 64
// double-buffered via register prefetch.
#define GPITCH 144
#define GCHUNKB (128 * GPITCH)
#define GBUFB (3 * GCHUNKB)                    // A | Bh | Bl
#define GEMM_SMEM (2 * GBUFB)                  // 110592

// AMODE: 1 = fp32 convert, 2 = split-K combine
// OMODE: 0 = fp32 out, 1 = fp16 hi/lo, 2 = fp16 single
template<int AMODE, int OMODE>
__device__ __forceinline__ void gemm_core(
    const float* __restrict__ Af,
    const __half* __restrict__ Bhi, const __half* __restrict__ Blo,
    float* __restrict__ Yf,
    __half* __restrict__ Yhi, __half* __restrict__ Ylo,
    char* smem) {
    const int bm = blockIdx.x * 128;
    const int bn = blockIdx.y * 128;
    const int tid = threadIdx.x;
    const int lane = tid & 31;
    const int wid = tid >> 5;
    const int wm = (wid & 3) * 32;
    const int wn = (wid >> 2) * 32;
    const uint32_t base = smem_u32(smem);

    float acc[2][4][4];
    #pragma unroll
    for (int mi = 0; mi < 2; mi++)
        #pragma unroll
        for (int ni = 0; ni < 4; ni++)
            #pragma unroll
            for (int k = 0; k < 4; k++) acc[mi][ni][k] = 0.f;

    const int a_row = lane & 15;
    const int a_kb  = (lane >> 4) * 16;
    const int pr0 = tid >> 3, pc0 = tid & 7;
    const int pr1 = (tid + 512) >> 3, pc1 = (tid + 512) & 7;

    float4 pf[6];
    #define PFLOAD(k0) do { \
        if (AMODE == 2) { \
            pf[0] = ld_comb8(bm + pr0, (k0) + pc0 * 8); \
            pf[3] = ld_comb8(bm + pr1, (k0) + pc1 * 8); \
        } else { \
            pf[0] = ld_cvt8(Af + (size_t)(bm + pr0) * E + (k0) + pc0 * 8); \
            pf[3] = ld_cvt8(Af + (size_t)(bm + pr1) * E + (k0) + pc1 * 8); \
        } \
        size_t g0 = (size_t)pr0 * E + (k0) + pc0 * 8; \
        size_t g1 = (size_t)pr1 * E + (k0) + pc1 * 8; \
        pf[1] = *(const float4*)(Bhi + (size_t)bn * E + g0); \
        pf[2] = *(const float4*)(Blo + (size_t)bn * E + g0); \
        pf[4] = *(const float4*)(Bhi + (size_t)bn * E + g1); \
        pf[5] = *(const float4*)(Blo + (size_t)bn * E + g1); \
    } while (0)
    #define PFSTORE(buf) do { \
        char* bp = smem + (buf) * GBUFB; \
        int s0 = pr0 * GPITCH + pc0 * 16; \
        int s1 = pr1 * GPITCH + pc1 * 16; \
        *(float4*)(bp + s0)               = pf[0]; \
        *(float4*)(bp + GCHUNKB + s0)     = pf[1]; \
        *(float4*)(bp + 2 * GCHUNKB + s0) = pf[2]; \
        *(float4*)(bp + s1)               = pf[3]; \
        *(float4*)(bp + GCHUNKB + s1)     = pf[4]; \
        *(float4*)(bp + 2 * GCHUNKB + s1) = pf[5]; \
    } while (0)

    PFLOAD(0);
    PFSTORE(0);
    __syncthreads();

    for (int kc = 0; kc < 4; kc++) {
        if (kc < 3) PFLOAD((kc + 1) * 64);
        const uint32_t uA = base + (kc & 1) * GBUFB;
        const uint32_t uB = uA + GCHUNKB;

        #pragma unroll
        for (int ks = 0; ks < 4; ks++) {
            const int kb = ks * 32;
            uint32_t a[2][4], bhi[4][2], blo[4][2];
            #pragma unroll
            for (int mi = 0; mi < 2; mi++) {
                uint32_t off = (uint32_t)((wm + mi * 16 + a_row) * GPITCH + kb + a_kb);
                ldsm4(a[mi], uA + off);
            }
            #pragma unroll
            for (int np = 0; np < 2; np++) {
                uint32_t off = (uint32_t)((wn + np * 16 + a_row) * GPITCH + kb + a_kb);
                uint32_t th[4], tl[4];
                ldsm4(th, uB + off);
                ldsm4(tl, uB + GCHUNKB + off);
                bhi[np*2][0] = th[0]; bhi[np*2][1] = th[2];
                bhi[np*2+1][0] = th[1]; bhi[np*2+1][1] = th[3];
                blo[np*2][0] = tl[0]; blo[np*2][1] = tl[2];
                blo[np*2+1][0] = tl[1]; blo[np*2+1][1] = tl[3];
            }
            #pragma unroll
            for (int mi = 0; mi < 2; mi++)
                #pragma unroll
                for (int ni = 0; ni < 4; ni++) {
                    mma16816h(acc[mi][ni], a[mi], bhi[ni][0], bhi[ni][1]);
                    mma16816h(acc[mi][ni], a[mi], blo[ni][0], blo[ni][1]);
                }
        }
        if (kc < 3) {
            PFSTORE((kc + 1) & 1);
            __syncthreads();
        }
    }

    const int g = lane >> 2;
    const int t2 = (lane & 3) * 2;
    #pragma unroll
    for (int mi = 0; mi < 2; mi++)
        #pragma unroll
        for (int ni = 0; ni < 4; ni++) {
            int row = bm + wm + mi * 16 + g;
            int col = bn + wn + ni * 8 + t2;
            float* ac = acc[mi][ni];
            if (OMODE == 0) {
                *(float2*)&Yf[(size_t)row * E + col] = make_float2(ac[0], ac[1]);
                *(float2*)&Yf[(size_t)(row + 8) * E + col] = make_float2(ac[2], ac[3]);
            } else if (OMODE == 2) {
                *(uint32_t*)(Yhi + (size_t)row * E + col) = pack_f16(ac[0], ac[1]);
                *(uint32_t*)(Yhi + (size_t)(row + 8) * E + col) = pack_f16(ac[2], ac[3]);
            } else {
                uint32_t h0, l0, h1, l1;
                split_pair_f16(ac[0], ac[1], h0, l0);
                split_pair_f16(ac[2], ac[3], h1, l1);
                *(uint32_t*)(Yhi + (size_t)row * E + col) = h0;
                *(uint32_t*)(Ylo + (size_t)row * E + col) = l0;
                *(uint32_t*)(Yhi + (size_t)(row + 8) * E + col) = h1;
                *(uint32_t*)(Ylo + (size_t)(row + 8) * E + col) = l1;
            }
        }
    #undef PFLOAD
    #undef PFSTORE
}

struct QKVOuts {
    __half *q, *kh, *kl, *v;
};

// fused Q/K/V projections from fp32 x: z=0 Q (fp16), z=1 K (hi/lo), z=2 V (fp16)
__global__ __launch_bounds__(512, 1)
void gemm_qkv(const float* __restrict__ x,
              const __half* __restrict__ whi, const __half* __restrict__ wlo,
              QKVOuts o) {
    extern __shared__ char smem[];
    const int z = blockIdx.z;
    const __half* Bh = whi + (size_t)z * E * E;
    const __half* Bl = wlo + (size_t)z * E * E;
    if (z == 0)
        gemm_core<1, 2>(x, Bh, Bl, nullptr, o.q, nullptr, smem);
    else if (z == 1)
        gemm_core<1, 1>(x, Bh, Bl, nullptr, o.kh, o.kl, smem);
    else
        gemm_core<1, 2>(x, Bh, Bl, nullptr, o.v, nullptr, smem);
}

// output GEMM with fused split-K combine + scramble on the A side
__global__ __launch_bounds__(512, 1)
void gemm_out(const __half* __restrict__ whi, const __half* __restrict__ wlo,
              float* __restrict__ Yf) {
    extern __shared__ char smem[];
    gemm_core<2, 0>(nullptr, whi, wlo, Yf, nullptr, nullptr, smem);
}

// ---------------- tensor-core varlen flash attention, split-K -----------------
// CTA: 128 queries of one (b,h) and a slice of its key range (NSPLIT=2).
// Q single fp16; K fp16 hi/lo (2-term QK); V single fp16; P single fp16.
// Fixed-base softmax p = 2^s; purely additive partials.
#define PQ 80
#define SM_KV (128 * PQ)                      // Q region: 10240
#define KVBUF (192 * PQ)                      // Khi|Klo|V, 64 rows each: 15360
#define ATTN_SMEM (SM_KV + 2 * KVBUF)         // 40960

__global__ __launch_bounds__(128, 2)
void attn_mma() {
    const int b = blockIdx.z / NSPLIT;
    const int sp = blockIdx.z % NSPLIT;
    const int h = blockIdx.y;
    const int L = g_len[b];
    const int qt = blockIdx.x * 128;
    if (qt >= L) return;

    extern __shared__ char sm[];
    const uint32_t uQh = smem_u32(sm);

    const int tid = threadIdx.x;
    const int lane = tid & 31;
    const int w = tid >> 5;
    const int wq = w * 32;
    const int g = lane >> 2;
    const int t2 = (lane & 3) * 2;

    const int pr = tid >> 2;
    const int pc = tid & 3;

    #define KV_ISSUE(k0, buf) do { \
        uint32_t dbase = uQh + SM_KV + (buf) * KVBUF; \
        _Pragma("unroll") \
        for (int i = 0; i < 6; i++) { \
            int r = pr + i * 32; \
            int region = r >> 6, rr = r & 63; \
            const __half* src = \
                (region == 0) ? g_khi : (region == 1) ? g_klo : g_v16; \
            cpasync16(dbase + r * PQ + pc * 16, \
                      src + ((size_t)(b * S + (k0) + rr)) * E + h * D + pc * 8); \
        } \
    } while (0)

    // key-tile range for this split
    const int ntiles = (L + 63) >> 6;
    const int chunk = (ntiles + NSPLIT - 1) / NSPLIT;
    const int t0 = sp * chunk;
    const int t1 = min(ntiles, t0 + chunk);

    // ---- stage Q tile (128 rows x 64B, single fp16) ----
    {
        int r = tid;
        size_t off = ((size_t)(b * S + qt + r)) * E + h * D;
        const uint4* sh = (const uint4*)(g_q16 + off);
        #pragma unroll
        for (int j = 0; j < 4; j++)
            *(uint4*)(sm + r * PQ + 16 * j) = sh[j];
    }
    if (t0 < t1) { KV_ISSUE(t0 * 64, t0 & 1); CP_COMMIT(); }
    __syncthreads();

    // Q fragments (kept in registers for the whole kernel)
    uint32_t qh[2][2][4];
    #pragma unroll
    for (int mi = 0; mi < 2; mi++)
        #pragma unroll
        for (int s = 0; s < 2; s++) {
            uint32_t ad = uQh + (wq + mi * 16 + (lane & 15)) * PQ
                        + (lane >> 4) * 16 + s * 32;
            ldsm4(qh[mi][s], ad);
        }

    float lsum[2][2], acc[2][4][4];
    #pragma unroll
    for (int mi = 0; mi < 2; mi++)
        #pragma unroll
        for (int hf = 0; hf < 2; hf++) lsum[mi][hf] = 0.f;
    #pragma unroll
    for (int mi = 0; mi < 2; mi++)
        #pragma unroll
        for (int nd = 0; nd < 4; nd++)
            #pragma unroll
            for (int c = 0; c < 4; c++) acc[mi][nd][c] = 0.f;

    for (int t = t0; t < t1; t++) {
        const int tn = min(64, L - t * 64);
        if (t + 1 < t1) {
            KV_ISSUE((t + 1) * 64, (t + 1) & 1);
            CP_COMMIT();
            CP_WAIT1();
        } else {
            CP_WAIT0();
        }
        __syncthreads();

        const uint32_t uK = uQh + SM_KV + (t & 1) * KVBUF;       // Khi
        const uint32_t uV = uK + 128 * PQ;                        // V

        // ---- scores: S[32q x 64k] per warp; Q single x K hi/lo (2 terms) ----
        float sc[2][8][4];
        #pragma unroll
        for (int mi = 0; mi < 2; mi++)
            #pragma unroll
            for (int nj = 0; nj < 8; nj++)
                #pragma unroll
                for (int c = 0; c < 4; c++) sc[mi][nj][c] = 0.f;

        #pragma unroll
        for (int njp = 0; njp < 4; njp++) {
            uint32_t kh[2][4], kl[2][4];
            #pragma unroll
            for (int s = 0; s < 2; s++) {
                uint32_t ad = uK + (njp * 16 + (lane & 15)) * PQ
                            + (lane >> 4) * 16 + s * 32;
                ldsm4(kh[s], ad);
                ldsm4(kl[s], ad + 64 * PQ);
            }
            #pragma unroll
            for (int mi = 0; mi < 2; mi++)
                #pragma unroll
                for (int j2 = 0; j2 < 2; j2++) {
                    float* dst = sc[mi][njp * 2 + j2];
                    #pragma unroll
                    for (int s = 0; s < 2; s++) {
                        mma16816h(dst, qh[mi][s], kh[s][j2], kh[s][2 + j2]);
                        mma16816h(dst, qh[mi][s], kl[s][j2], kl[s][2 + j2]);
                    }
                }
        }

        // ---- mask tail keys ----
        if (tn < 64) {
            #pragma unroll
            for (int mi = 0; mi < 2; mi++)
                #pragma unroll
                for (int nj = 0; nj < 8; nj++)
                    #pragma unroll
                    for (int c = 0; c < 4; c++) {
                        int kc = nj * 8 + t2 + (c & 1);
                        if (kc >= tn) sc[mi][nj][c] = -1e30f;
                    }
        }

        // ---- fixed-base softmax: p = 2^s ----
        #pragma unroll
        for (int mi = 0; mi < 2; mi++)
            #pragma unroll
            for (int hf = 0; hf < 2; hf++) {
                float rowsum = 0.f;
                #pragma unroll
                for (int nj = 0; nj < 8; nj++) {
                    float p0 = ex2(sc[mi][nj][hf * 2]);
                    float p1 = ex2(sc[mi][nj][hf * 2 + 1]);
                    sc[mi][nj][hf * 2] = p0;
                    sc[mi][nj][hf * 2 + 1] = p1;
                    rowsum += p0 + p1;
                }
                rowsum += __shfl_xor_sync(0xffffffffu, rowsum, 1);
                rowsum += __shfl_xor_sync(0xffffffffu, rowsum, 2);
                lsum[mi][hf] += rowsum;
            }

        // ---- PV: O += P * V; P single fp16, V single fp16 ----
        #pragma unroll
        for (int s = 0; s < 4; s++) {          // k16 steps
            uint32_t ph[2][4];
            #pragma unroll
            for (int mi = 0; mi < 2; mi++) {
                float* c0 = sc[mi][2 * s];
                float* c1 = sc[mi][2 * s + 1];
                ph[mi][0] = pack_f16(c0[0], c0[1]);
                ph[mi][1] = pack_f16(c0[2], c0[3]);
                ph[mi][2] = pack_f16(c1[0], c1[1]);
                ph[mi][3] = pack_f16(c1[2], c1[3]);
            }
            #pragma unroll
            for (int dp = 0; dp < 2; dp++) {   // d-octet pairs
                uint32_t ad = uV + (s * 16 + (lane & 7) + ((lane >> 3) & 1) * 8) * PQ
                            + dp * 32 + (lane >> 4) * 16;
                uint32_t vh[4];
                ldsm4t(vh, ad);
                #pragma unroll
                for (int mi = 0; mi < 2; mi++) {
                    mma16816h(acc[mi][2*dp],   ph[mi], vh[0], vh[1]);
                    mma16816h(acc[mi][2*dp+1], ph[mi], vh[2], vh[3]);
                }
            }
        }
        __syncthreads();                       // buffer reuse safety
    }

    // ---- epilogue: raw fp32 partials (acc, lsum) to scratch ----
    #pragma unroll
    for (int mi = 0; mi < 2; mi++)
        #pragma unroll
        for (int hf = 0; hf < 2; hf++) {
            int q = qt + wq + mi * 16 + g + hf * 8;
            if (q < L) {
                size_t abase = (size_t)sp * M * E
                             + ((size_t)(b * S + q)) * E + h * D;
                #pragma unroll
                for (int nd = 0; nd < 4; nd++)
                    *(float2*)&g_pacc[abase + nd * 8 + t2] =
                        make_float2(acc[mi][nd][hf * 2], acc[mi][nd][hf * 2 + 1]);
                if ((lane & 3) == 0)
                    g_plsum[(size_t)sp * (B * S * H)
                            + ((size_t)(b * S + q)) * H + h] = lsum[mi][hf];
            }
        }
    #undef KV_ISSUE
}

// ---------------- launch ------------------------------------------------------
extern "C" void kernel_launch(void* const* d_in, const int* in_sizes, int n_in,
                              void* d_out, int out_size) {
    const float* x    = (const float*)d_in[0];
    const int*   mask = (const int*)  d_in[1];
    const float* Wq   = (const float*)d_in[2];
    const float* Wk   = (const float*)d_in[3];
    const float* Wv   = (const float*)d_in[4];
    const float* Wo   = (const float*)d_in[5];
    float* out = (float*)d_out;

    __half *q16, *khi, *klo, *v16, *whi, *wlo;
    cudaGetSymbolAddress((void**)&q16, g_q16);
    cudaGetSymbolAddress((void**)&khi, g_khi);
    cudaGetSymbolAddress((void**)&klo, g_klo);
    cudaGetSymbolAddress((void**)&v16, g_v16);
    cudaGetSymbolAddress((void**)&whi, g_whi);
    cudaGetSymbolAddress((void**)&wlo, g_wlo);

    cudaFuncSetAttribute(gemm_qkv, cudaFuncAttributeMaxDynamicSharedMemorySize,
                         GEMM_SMEM);
    cudaFuncSetAttribute(gemm_out, cudaFuncAttributeMaxDynamicSharedMemorySize,
                         GEMM_SMEM);
    cudaFuncSetAttribute(attn_mma, cudaFuncAttributeMaxDynamicSharedMemorySize,
                         ATTN_SMEM);

    len_kernel<<<B, 256>>>(mask);
    decompw_kernel<<<dim3(E*E/4/256, 4), 256>>>(Wq, Wk, Wv, Wo, whi, wlo);

    QKVOuts o = { q16, khi, klo, v16 };
    dim3 gq(M / 128, E / 128, 3);
    gemm_qkv<<<gq, 512, GEMM_SMEM>>>(x, whi, wlo, o);

    dim3 ga(S / 128, H, B * NSPLIT);
    attn_mma<<<ga, 128, ATTN_SMEM>>>();

    dim3 gg(M / 128, E / 128);
    gemm_out<<<gg, 512, GEMM_SMEM>>>(whi + 3*E*E, wlo + 3*E*E, out);
}